// round 8
// baseline (speedup 1.0000x reference)
#include <cuda_runtime.h>
#include <cstdlib>

// Problem dims: [B=2, C=1, D=160, H=192, W=160] fp32
#define W_   160
#define H_   192
#define D_   160
#define NB   2
#define HW_  (H_ * W_)
#define NTOT (NB * D_ * HW_)

// Tile: 32 x 16 outputs, 512 threads, z-chunk 40, 2 slices per barrier segment
#define TX   32
#define TY   16
#define IXW  40
#define IYH  24
#define RYH  32
#define ZC   40
#define CZ   4
#define GX   5
#define GY   12
#define NBLK (GX * GY * CZ * NB)   // 480
#define RING 11

#define P_IN  41
#define P_OUT 33

// Smem layout (float offsets)
#define SZ_XB_SL  (IYH * P_IN)                  // 984
#define OFF_RXB   0                             // inputs ring: 2f x 11 x 984
#define SZ_PX_SL  (TY * P_OUT)                  // 528
#define OFF_RPXB  (OFF_RXB + 2*RING*SZ_XB_SL)   // products ring: 3f x 11 x 528
#define OFF_TMP   (OFF_RPXB + 3*RING*SZ_PX_SL)  // union scratch
#define TMP_FS    (RYH * P_IN + 1)              // 1313 ; x-boxed inputs: 2 slices x 2 fields
#define TMP2_FS   (IYH * P_OUT + 1)             // 793  ; x-boxed products: 2 slices x 3 fields
#define OFF_PROD  (OFF_TMP + 4*TMP_FS)          // products: 2 slices x 3 fields x 984
#define SMEM_FL   (OFF_PROD + 6*SZ_XB_SL)       // 50228 floats
#define SMEM_BYTES (SMEM_FL * 4)                // 200912 B

__device__ float g_block[NBLK];
__device__ int   g_count;

__device__ __forceinline__ int iclampi(int v, int lo, int hi) {
    return v < lo ? lo : (v > hi ? hi : v);
}

__global__ void __launch_bounds__(512, 1)
lncc_fused_kernel(const float* __restrict__ yt, const float* __restrict__ yp,
                  float* __restrict__ out)
{
    extern __shared__ float sm[];
    __shared__ int s_last;
    __shared__ double wsd[16];

    const int tid = threadIdx.x;
    const int x0 = blockIdx.x * TX;
    const int y0 = blockIdx.y * TY;
    const int cz = blockIdx.z & 3;
    const int b  = blockIdx.z >> 2;
    const int z0 = cz * ZC;

    const float* __restrict__ bT = yt + (long)b * D_ * HW_;
    const float* __restrict__ bP = yp + (long)b * D_ * HW_;

    const int pLo = max(z0 - 4, 0);
    const int pHi = min(z0 + ZC + 3, D_ - 1);
    int zx = max(pLo - 4, 0);
    int next_out = z0;
    float rSn = 0.f, rSt = 0.f, rSp = 0.f;
    float acc = 0.f;
    const int aOut = (tid >> 5) * P_OUT + (tid & 31);
    const float inv_win = 1.0f / 729.0f;
    const float eps = 1e-6f;

    // Stage-1 x-box worker constants: per slice 256 units = 2f x 32rows x 4segs(10 out)
    const int s1_seg = tid & 3;
    const int s1_row = (tid >> 2) & 31;
    const int s1_f   = (tid >> 7) & 1;
    const int s1_gy  = iclampi(y0 - 8 + s1_row, 0, H_ - 1);
    const float* __restrict__ s1_base = (s1_f ? bP : bT) + (long)s1_gy * W_;
    const int s1_xb0 = x0 + s1_seg * 10 - 8;

    // Stage-2 fixed elem mapping (register z-window state)
    const int e_n = (tid < IXW * IYH - 512) ? 2 : 1;
    long e_go[2]; int e_a[2];
    #pragma unroll
    for (int q = 0; q < 2; ++q) {
        int e = tid + q * 512;
        if (e >= IXW * IYH) e = IXW * IYH - 1;
        int y = e / IXW, x = e - y * IXW;
        e_a[q] = y * P_IN + x;
        int gx = iclampi(x0 - 4 + x, 0, W_ - 1);
        int gy = iclampi(y0 - 4 + y, 0, H_ - 1);
        e_go[q] = (long)gy * W_ + gx;
    }
    float zst[2] = {0.f, 0.f}, zsp[2] = {0.f, 0.f};

    for (int zpA = pLo; zpA <= pHi; zpA += 2) {
        const int nzp = (zpA + 1 <= pHi) ? 2 : 1;
        const int zpB = zpA + nzp - 1;
        const int need = min(zpB + 4, D_ - 1);

        // ---- Stage 1: xy-box up to 2 input slices per pass into the ring ----
        while (zx <= need) {
            const int ns = min(2, need - zx + 1);
            // x-box from gmem: ns*256 units (1/thread at ns=2)
            if (tid < ns * 256) {
                const int slice = tid >> 8;
                const float* __restrict__ rowp = s1_base + (long)(zx + slice) * HW_;
                float v[18];
                #pragma unroll
                for (int k = 0; k < 18; ++k)
                    v[k] = rowp[iclampi(s1_xb0 + k, 0, W_ - 1)];
                float o[10];
                float S = v[0]+v[1]+v[2]+v[3]+v[4]+v[5]+v[6]+v[7]+v[8];
                o[0] = S;
                #pragma unroll
                for (int j = 1; j < 10; ++j) { S += v[j + 8] - v[j - 1]; o[j] = S; }
                if (x0 == 0 && s1_seg == 0)       { o[0]=o[4]; o[1]=o[4]; o[2]=o[4]; o[3]=o[4]; }
                if (x0 == W_ - TX && s1_seg == 3) { o[6]=o[5]; o[7]=o[5]; o[8]=o[5]; o[9]=o[5]; }
                int dst = OFF_TMP + (slice * 2 + s1_f) * TMP_FS + s1_row * P_IN + s1_seg * 10;
                #pragma unroll
                for (int j = 0; j < 10; ++j) sm[dst + j] = o[j];
            }
            __syncthreads();
            // y-box -> ring: ns*240 units = per slice 2f x 3segs(8 out) x 40 cols
            if (tid < ns * 240) {
                const int slice = tid / 240;
                int rest = tid - slice * 240;
                int c = rest % 40, q = rest / 40;
                int sg = q % 3, f = q / 3;
                int src = OFF_TMP + (slice * 2 + f) * TMP_FS + (sg * 8) * P_IN + c;
                float t[16];
                #pragma unroll
                for (int k = 0; k < 16; ++k) t[k] = sm[src + k * P_IN];
                float o[8];
                float S = t[0]+t[1]+t[2]+t[3]+t[4]+t[5]+t[6]+t[7]+t[8];
                o[0] = S;
                #pragma unroll
                for (int j = 1; j < 8; ++j) { S += t[j + 8] - t[j - 1]; o[j] = S; }
                if (y0 == 0 && sg == 0)       { o[0]=o[4]; o[1]=o[4]; o[2]=o[4]; o[3]=o[4]; }
                if (y0 == H_ - TY && sg == 2) { o[4]=o[3]; o[5]=o[3]; o[6]=o[3]; o[7]=o[3]; }
                const int slot = (zx + slice) % RING;
                int dst = OFF_RXB + (f * RING + slot) * SZ_XB_SL + (sg * 8) * P_IN + c;
                #pragma unroll
                for (int j = 0; j < 8; ++j) sm[dst + j * P_IN] = o[j];
            }
            __syncthreads();
            zx += ns;
        }

        // ---- Stage 2: z-mean advance + centered products for nzp slices ----
        #pragma unroll
        for (int sz = 0; sz < 2; ++sz) {
            if (sz < nzp) {
                const int z = zpA + sz;
                const long sb = (long)z * HW_;
                if (z == pLo) {
                    int sl[9];
                    #pragma unroll
                    for (int k = 0; k < 9; ++k) sl[k] = iclampi(z - 4 + k, 0, D_ - 1) % RING;
                    #pragma unroll
                    for (int q = 0; q < 2; ++q) {
                        if (q < e_n) {
                            int a = e_a[q];
                            float st = 0.f, sp = 0.f;
                            #pragma unroll
                            for (int k = 0; k < 9; ++k) {
                                st += sm[OFF_RXB + sl[k] * SZ_XB_SL + a];
                                sp += sm[OFF_RXB + (RING + sl[k]) * SZ_XB_SL + a];
                            }
                            zst[q] = st; zsp[q] = sp;
                            float t = bT[sb + e_go[q]], p = bP[sb + e_go[q]];
                            float tc = t - st * inv_win, pc = p - sp * inv_win;
                            sm[OFF_PROD + (sz * 3 + 0) * SZ_XB_SL + a] = tc * pc;
                            sm[OFF_PROD + (sz * 3 + 1) * SZ_XB_SL + a] = tc * tc;
                            sm[OFF_PROD + (sz * 3 + 2) * SZ_XB_SL + a] = pc * pc;
                        }
                    }
                } else {
                    const int sN = (min(z + 4, D_ - 1)) % RING;
                    const int sO = (max(z - 5, 0)) % RING;
                    #pragma unroll
                    for (int q = 0; q < 2; ++q) {
                        if (q < e_n) {
                            int a = e_a[q];
                            float st = zst[q] + sm[OFF_RXB + sN * SZ_XB_SL + a]
                                              - sm[OFF_RXB + sO * SZ_XB_SL + a];
                            float sp = zsp[q] + sm[OFF_RXB + (RING + sN) * SZ_XB_SL + a]
                                              - sm[OFF_RXB + (RING + sO) * SZ_XB_SL + a];
                            zst[q] = st; zsp[q] = sp;
                            float t = bT[sb + e_go[q]], p = bP[sb + e_go[q]];
                            float tc = t - st * inv_win, pc = p - sp * inv_win;
                            sm[OFF_PROD + (sz * 3 + 0) * SZ_XB_SL + a] = tc * pc;
                            sm[OFF_PROD + (sz * 3 + 1) * SZ_XB_SL + a] = tc * tc;
                            sm[OFF_PROD + (sz * 3 + 2) * SZ_XB_SL + a] = pc * pc;
                        }
                    }
                }
            }
        }
        __syncthreads();

        // ---- Stage 3a: x-box products: nzp*288 units = slice x 3f x 24rows x 4segs(8) ----
        #pragma unroll
        for (int uu = 0; uu < 2; ++uu) {
            int u = tid + uu * 512;
            if (u < nzp * 288) {
                int seg = u & 3, rest = u >> 2;
                int r = rest % 24, rest2 = rest / 24;
                int f = rest2 % 3, slice = rest2 / 3;
                int src = OFF_PROD + (slice * 3 + f) * SZ_XB_SL + r * P_IN + seg * 8;
                float t[16];
                #pragma unroll
                for (int k = 0; k < 16; ++k) t[k] = sm[src + k];
                int dst = OFF_TMP + (slice * 3 + f) * TMP2_FS + r * P_OUT + seg * 8;
                float S = t[0]+t[1]+t[2]+t[3]+t[4]+t[5]+t[6]+t[7]+t[8];
                sm[dst] = S;
                #pragma unroll
                for (int j = 1; j < 8; ++j) { S += t[j + 8] - t[j - 1]; sm[dst + j] = S; }
            }
        }
        __syncthreads();
        // ---- Stage 3b: y-box products -> ring: nzp*192 units = slice x 3f x 2segs(8) x 32c ----
        if (tid < nzp * 192) {
            int c = tid % 32, rest = tid / 32;
            int sg = rest % 2, rest2 = rest / 2;
            int f = rest2 % 3, slice = rest2 / 3;
            int src = OFF_TMP + (slice * 3 + f) * TMP2_FS + (sg * 8) * P_OUT + c;
            float t[16];
            #pragma unroll
            for (int k = 0; k < 16; ++k) t[k] = sm[src + k * P_OUT];
            const int slot = (zpA + slice) % RING;
            int dst = OFF_RPXB + (f * RING + slot) * SZ_PX_SL + (sg * 8) * P_OUT + c;
            float S = t[0]+t[1]+t[2]+t[3]+t[4]+t[5]+t[6]+t[7]+t[8];
            sm[dst] = S;
            #pragma unroll
            for (int j = 1; j < 8; ++j) { S += t[j + 8] - t[j - 1]; sm[dst + j * P_OUT] = S; }
        }
        __syncthreads();

        // ---- Emit ready output slices ----
        while (next_out < z0 + ZC && min(next_out + 4, D_ - 1) <= zpB) {
            if (next_out == z0) {
                rSn = rSt = rSp = 0.f;
                #pragma unroll
                for (int k = 0; k < 9; ++k) {
                    int s = iclampi(next_out - 4 + k, 0, D_ - 1) % RING;
                    rSn += sm[OFF_RPXB + s * SZ_PX_SL + aOut];
                    rSt += sm[OFF_RPXB + (RING + s) * SZ_PX_SL + aOut];
                    rSp += sm[OFF_RPXB + (2 * RING + s) * SZ_PX_SL + aOut];
                }
            } else {
                int sN = (min(next_out + 4, D_ - 1)) % RING;
                int sO = (max(next_out - 5, 0)) % RING;
                rSn += sm[OFF_RPXB + sN * SZ_PX_SL + aOut] - sm[OFF_RPXB + sO * SZ_PX_SL + aOut];
                rSt += sm[OFF_RPXB + (RING + sN) * SZ_PX_SL + aOut] - sm[OFF_RPXB + (RING + sO) * SZ_PX_SL + aOut];
                rSp += sm[OFF_RPXB + (2 * RING + sN) * SZ_PX_SL + aOut] - sm[OFF_RPXB + (2 * RING + sO) * SZ_PX_SL + aOut];
            }
            float cc = (rSn * rSn + eps) / (rSt * rSp + eps);
            acc += fminf(fmaxf(cc, 0.f), 1.f);
            ++next_out;
        }
    }

    // ---- Per-block reduction (deterministic fixed tree) ----
    __syncthreads();
    float v = acc;
    #pragma unroll
    for (int o = 16; o; o >>= 1) v += __shfl_down_sync(0xffffffffu, v, o);
    if ((tid & 31) == 0) sm[tid >> 5] = v;
    __syncthreads();
    const int flat = blockIdx.x + GX * (blockIdx.y + GY * blockIdx.z);
    if (tid < 16) {
        float t = sm[tid];
        #pragma unroll
        for (int o = 8; o; o >>= 1) t += __shfl_down_sync(0xffffu, t, o);
        if (tid == 0) g_block[flat] = t;
    }

    // ---- Last block finalizes ----
    __threadfence();
    if (tid == 0) {
        int old = atomicAdd(&g_count, 1);
        s_last = (old == NBLK - 1);
    }
    __syncthreads();
    if (s_last) {
        double d = (tid < NBLK) ? (double)g_block[tid] : 0.0;
        #pragma unroll
        for (int o = 16; o; o >>= 1) d += __shfl_down_sync(0xffffffffu, d, o);
        if ((tid & 31) == 0) wsd[tid >> 5] = d;
        __syncthreads();
        if (tid < 16) {
            double t2 = wsd[tid];
            #pragma unroll
            for (int o = 8; o; o >>= 1) t2 += __shfl_down_sync(0xffffu, t2, o);
            if (tid == 0) {
                out[0] = (float)(-t2 / (double)NTOT);
                g_count = 0;
            }
        }
    }
}

namespace {
struct KInit {
    KInit() {
        setenv("CUDA_MODULE_LOADING", "EAGER", 1);
        cudaFuncSetAttribute(lncc_fused_kernel,
                             cudaFuncAttributeMaxDynamicSharedMemorySize, SMEM_BYTES);
        cudaFuncAttributes a;
        cudaFuncGetAttributes(&a, lncc_fused_kernel);
    }
};
KInit kinit_;
}

extern "C" void kernel_launch(void* const* d_in, const int* in_sizes, int n_in,
                              void* d_out, int out_size)
{
    const float* y_true = (const float*)d_in[0];
    const float* y_pred = (const float*)d_in[1];
    float* out = (float*)d_out;
    (void)in_sizes; (void)n_in; (void)out_size;

    cudaFuncSetAttribute(lncc_fused_kernel,
                         cudaFuncAttributeMaxDynamicSharedMemorySize, SMEM_BYTES);
    dim3 grid(GX, GY, CZ * NB);
    lncc_fused_kernel<<<grid, 512, SMEM_BYTES>>>(y_true, y_pred, out);
}

// round 9
// speedup vs baseline: 1.0286x; 1.0286x over previous
#include <cuda_runtime.h>
#include <cstdlib>

// Problem dims: [B=2, C=1, D=160, H=192, W=160] fp32
#define W_   160
#define H_   192
#define D_   160
#define NB   2
#define HW_  (H_ * W_)
#define NTOT (NB * D_ * HW_)

// Tile: 32 x 16 outputs, 512 threads, z-chunk 40 (R7 geometry)
#define TX   32
#define TY   16
#define IXW  40      // inner width  (out + 8)
#define IYH  24      // inner height (out + 8)
#define RYH  32      // raw rows (inner + 8)
#define RXW  48      // raw taps per row (inner + 8)
#define ZC   40
#define CZ   4
#define GX   5
#define GY   12
#define NBLK (GX * GY * CZ * NB)   // 480

#define P_IN  41
#define P_OUT 33
#define P_STG 49

// Smem layout (float offsets)
#define OFF_RXB   0                            // xy-boxed inputs ring: 2 x 10 x (24*41)
#define SZ_XB_SL  (IYH * P_IN)                 // 984
#define OFF_RPXB  (OFF_RXB + 2*10*SZ_XB_SL)    // xy-boxed products ring: 3 x 10 x (16*33)
#define SZ_PX_SL  (TY * P_OUT)                 // 528
#define OFF_TMP   (OFF_RPXB + 3*10*SZ_PX_SL)   // x-boxed scratch (union)
#define TMP_FS    (RYH * P_IN + 1)             // 1313 (inputs, 2 fields)
#define TMP2_FS   (IYH * P_OUT + 1)            // 793  (products, 3 fields)
#define OFF_PROD  (OFF_TMP + 2*TMP_FS)
#define OFF_STG   (OFF_PROD + 3*SZ_XB_SL)      // raw staging: 2 x (32*49+1)
#define STG_FS    (RYH * P_STG + 1)            // 1569
#define SMEM_FL   (OFF_STG + 2*STG_FS)         // 44236 floats
#define SMEM_BYTES (SMEM_FL * 4)               // 176944 B

__device__ float g_block[NBLK];
__device__ int   g_count;

__device__ __forceinline__ int iclampi(int v, int lo, int hi) {
    return v < lo ? lo : (v > hi ? hi : v);
}

__global__ void __launch_bounds__(512, 1)
lncc_fused_kernel(const float* __restrict__ yt, const float* __restrict__ yp,
                  float* __restrict__ out)
{
    extern __shared__ float sm[];
    __shared__ int s_last;
    __shared__ double wsd[16];

    const int tid = threadIdx.x;
    const int x0 = blockIdx.x * TX;
    const int y0 = blockIdx.y * TY;
    const int cz = blockIdx.z & 3;
    const int b  = blockIdx.z >> 2;
    const int z0 = cz * ZC;

    const float* __restrict__ bT = yt + (long)b * D_ * HW_;
    const float* __restrict__ bP = yp + (long)b * D_ * HW_;

    const int pLo = max(z0 - 4, 0);
    const int pHi = min(z0 + ZC + 3, D_ - 1);
    int zx = max(pLo - 4, 0);
    int next_out = z0;
    float rSn = 0.f, rSt = 0.f, rSp = 0.f;
    float acc = 0.f;
    const int aOut = (tid >> 5) * P_OUT + (tid & 31);
    const float inv_win = 1.0f / 729.0f;
    const float eps = 1e-6f;

    // Staging-load per-thread constants: 6 elems, i = tid + k*512 over 2*32*48
    long stg_go[6]; int stg_a[6];
    #pragma unroll
    for (int k = 0; k < 6; ++k) {
        int i = tid + k * 512;
        int f = i / (RYH * RXW), rest = i % (RYH * RXW);
        int r = rest / RXW, x = rest % RXW;
        int gx = iclampi(x0 - 8 + x, 0, W_ - 1);
        int gy = iclampi(y0 - 8 + r, 0, H_ - 1);
        stg_go[k] = (f ? (long)NTOT / 2 * 0 : 0) + (long)gy * W_ + gx;  // field handled below
        stg_a[k]  = f * STG_FS + r * P_STG + x;
        // encode field in sign-free aux: store f in low bit of a separate array
        // (we keep f implicit: k<3 ? depends on tid) -- recompute f at use instead
    }
    // field per staging elem (constant per thread per k)
    int stg_f[6];
    #pragma unroll
    for (int k = 0; k < 6; ++k) stg_f[k] = (tid + k * 512) / (RYH * RXW);

    // Stage-1 x-box worker constants: 512 = 2 fields x 32 rows x 8 segs(5 out)
    const int s1_f = tid >> 8;
    const int s1_r = (tid & 255) >> 3;
    const int s1_s = tid & 7;
    const int s1_src = OFF_STG + s1_f * STG_FS + s1_r * P_STG + s1_s * 5;
    const int s1_dst = OFF_TMP + s1_f * TMP_FS + s1_r * P_IN + s1_s * 5;

    // Stage-2 fixed elem mapping (register z-window state)
    const int e_n = (tid < IXW * IYH - 512) ? 2 : 1;
    long e_go[2]; int e_a[2];
    #pragma unroll
    for (int q = 0; q < 2; ++q) {
        int e = tid + q * 512;
        if (e >= IXW * IYH) e = IXW * IYH - 1;
        int y = e / IXW, x = e - y * IXW;
        e_a[q] = y * P_IN + x;
        int gx = iclampi(x0 - 4 + x, 0, W_ - 1);
        int gy = iclampi(y0 - 4 + y, 0, H_ - 1);
        e_go[q] = (long)gy * W_ + gx;
    }
    float zst[2] = {0.f, 0.f}, zsp[2] = {0.f, 0.f};

    for (int zp = pLo; zp <= pHi; ++zp) {
        const int need = min(zp + 4, D_ - 1);

        // ---- Stage 1: xy-box input slice(s) into ring ----
        while (zx <= need) {
            // 1a: coalesced staging of raw slice zx (x,y clamped baked in)
            {
                const long sb = (long)zx * HW_;
                #pragma unroll
                for (int k = 0; k < 6; ++k) {
                    const float* __restrict__ src = stg_f[k] ? bP : bT;
                    sm[OFF_STG + stg_a[k]] = src[sb + stg_go[k]];
                }
            }
            __syncthreads();
            // 1b: x-box from staged smem, register-sliding (5 outputs/thread)
            {
                float v[13];
                #pragma unroll
                for (int k = 0; k < 13; ++k) v[k] = sm[s1_src + k];
                float o[5];
                float S = v[0]+v[1]+v[2]+v[3]+v[4]+v[5]+v[6]+v[7]+v[8];
                o[0] = S;
                #pragma unroll
                for (int j = 1; j < 5; ++j) { S += v[j + 8] - v[j - 1]; o[j] = S; }
                if (x0 == 0 && s1_s == 0)       { o[0]=o[4]; o[1]=o[4]; o[2]=o[4]; o[3]=o[4]; }
                if (x0 == W_ - TX && s1_s == 7) { o[1]=o[0]; o[2]=o[0]; o[3]=o[0]; o[4]=o[0]; }
                #pragma unroll
                for (int j = 0; j < 5; ++j) sm[s1_dst + j] = o[j];
            }
            __syncthreads();
            // 1c: y-box -> ring slot: 240 workers = 2f x 3 segs(8 out) x 40 cols
            {
                const int slot = zx % 10;
                if (tid < 240) {
                    int c = tid % 40, q = tid / 40;
                    int sg = q % 3, f = q / 3;
                    int src = OFF_TMP + f * TMP_FS + (sg * 8) * P_IN + c;
                    float t[16];
                    #pragma unroll
                    for (int k = 0; k < 16; ++k) t[k] = sm[src + k * P_IN];
                    float o[8];
                    float S = t[0]+t[1]+t[2]+t[3]+t[4]+t[5]+t[6]+t[7]+t[8];
                    o[0] = S;
                    #pragma unroll
                    for (int j = 1; j < 8; ++j) { S += t[j + 8] - t[j - 1]; o[j] = S; }
                    if (y0 == 0 && sg == 0)       { o[0]=o[4]; o[1]=o[4]; o[2]=o[4]; o[3]=o[4]; }
                    if (y0 == H_ - TY && sg == 2) { o[4]=o[3]; o[5]=o[3]; o[6]=o[3]; o[7]=o[3]; }
                    int dst = OFF_RXB + (f * 10 + slot) * SZ_XB_SL + (sg * 8) * P_IN + c;
                    #pragma unroll
                    for (int j = 0; j < 8; ++j) sm[dst + j * P_IN] = o[j];
                }
            }
            __syncthreads();
            ++zx;
        }

        // ---- Stage 2: z-mean advance (register state) + centered products ----
        {
            const long sb = (long)zp * HW_;
            if (zp == pLo) {
                int sl[9];
                #pragma unroll
                for (int k = 0; k < 9; ++k) sl[k] = iclampi(zp - 4 + k, 0, D_ - 1) % 10;
                #pragma unroll
                for (int q = 0; q < 2; ++q) {
                    if (q < e_n) {
                        int a = e_a[q];
                        float st = 0.f, sp = 0.f;
                        #pragma unroll
                        for (int k = 0; k < 9; ++k) {
                            st += sm[OFF_RXB + sl[k] * SZ_XB_SL + a];
                            sp += sm[OFF_RXB + (10 + sl[k]) * SZ_XB_SL + a];
                        }
                        zst[q] = st; zsp[q] = sp;
                        float t = bT[sb + e_go[q]], p = bP[sb + e_go[q]];
                        float tc = t - st * inv_win, pc = p - sp * inv_win;
                        sm[OFF_PROD + a]                = tc * pc;
                        sm[OFF_PROD + SZ_XB_SL + a]     = tc * tc;
                        sm[OFF_PROD + 2 * SZ_XB_SL + a] = pc * pc;
                    }
                }
            } else {
                const int sN = (min(zp + 4, D_ - 1)) % 10;
                const int sO = (max(zp - 5, 0)) % 10;
                #pragma unroll
                for (int q = 0; q < 2; ++q) {
                    if (q < e_n) {
                        int a = e_a[q];
                        float st = zst[q] + sm[OFF_RXB + sN * SZ_XB_SL + a]
                                          - sm[OFF_RXB + sO * SZ_XB_SL + a];
                        float sp = zsp[q] + sm[OFF_RXB + (10 + sN) * SZ_XB_SL + a]
                                          - sm[OFF_RXB + (10 + sO) * SZ_XB_SL + a];
                        zst[q] = st; zsp[q] = sp;
                        float t = bT[sb + e_go[q]], p = bP[sb + e_go[q]];
                        float tc = t - st * inv_win, pc = p - sp * inv_win;
                        sm[OFF_PROD + a]                = tc * pc;
                        sm[OFF_PROD + SZ_XB_SL + a]     = tc * tc;
                        sm[OFF_PROD + 2 * SZ_XB_SL + a] = pc * pc;
                    }
                }
            }
        }
        __syncthreads();

        // ---- Stage 3a: x-box products: 288 = 3f x 24 rows x 4 segs(8 out) ----
        if (tid < 288) {
            int s = tid & 3, rest = tid >> 2;
            int r = rest % 24, f = rest / 24;
            int src = OFF_PROD + f * SZ_XB_SL + r * P_IN + s * 8;
            float t[16];
            #pragma unroll
            for (int k = 0; k < 16; ++k) t[k] = sm[src + k];
            int dst = OFF_TMP + f * TMP2_FS + r * P_OUT + s * 8;
            float S = t[0]+t[1]+t[2]+t[3]+t[4]+t[5]+t[6]+t[7]+t[8];
            sm[dst] = S;
            #pragma unroll
            for (int j = 1; j < 8; ++j) { S += t[j + 8] - t[j - 1]; sm[dst + j] = S; }
        }
        __syncthreads();
        // ---- Stage 3b: y-box products -> ring: 384 = 3f x 4 segs(4 out) x 32 cols ----
        {
            const int slot = zp % 10;
            if (tid < 384) {
                int c = tid % 32, rest = tid / 32;
                int sg = rest & 3, f = rest >> 2;
                int src = OFF_TMP + f * TMP2_FS + (sg * 4) * P_OUT + c;
                float t[12];
                #pragma unroll
                for (int k = 0; k < 12; ++k) t[k] = sm[src + k * P_OUT];
                int dst = OFF_RPXB + (f * 10 + slot) * SZ_PX_SL + (sg * 4) * P_OUT + c;
                float S = t[0]+t[1]+t[2]+t[3]+t[4]+t[5]+t[6]+t[7]+t[8];
                sm[dst] = S;
                #pragma unroll
                for (int j = 1; j < 4; ++j) {
                    S += t[j + 8] - t[j - 1];
                    sm[dst + j * P_OUT] = S;
                }
            }
        }
        __syncthreads();

        // ---- Emit ready output slices (thread owns one output elem) ----
        while (next_out < z0 + ZC && min(next_out + 4, D_ - 1) <= zp) {
            if (next_out == z0) {
                rSn = rSt = rSp = 0.f;
                #pragma unroll
                for (int k = 0; k < 9; ++k) {
                    int s = iclampi(next_out - 4 + k, 0, D_ - 1) % 10;
                    rSn += sm[OFF_RPXB + s * SZ_PX_SL + aOut];
                    rSt += sm[OFF_RPXB + (10 + s) * SZ_PX_SL + aOut];
                    rSp += sm[OFF_RPXB + (20 + s) * SZ_PX_SL + aOut];
                }
            } else {
                int sN = (min(next_out + 4, D_ - 1)) % 10;
                int sO = (max(next_out - 5, 0)) % 10;
                rSn += sm[OFF_RPXB + sN * SZ_PX_SL + aOut] - sm[OFF_RPXB + sO * SZ_PX_SL + aOut];
                rSt += sm[OFF_RPXB + (10 + sN) * SZ_PX_SL + aOut] - sm[OFF_RPXB + (10 + sO) * SZ_PX_SL + aOut];
                rSp += sm[OFF_RPXB + (20 + sN) * SZ_PX_SL + aOut] - sm[OFF_RPXB + (20 + sO) * SZ_PX_SL + aOut];
            }
            float cc = (rSn * rSn + eps) / (rSt * rSp + eps);
            acc += fminf(fmaxf(cc, 0.f), 1.f);
            ++next_out;
        }
    }

    // ---- Per-block reduction (deterministic fixed tree) ----
    __syncthreads();
    float v = acc;
    #pragma unroll
    for (int o = 16; o; o >>= 1) v += __shfl_down_sync(0xffffffffu, v, o);
    if ((tid & 31) == 0) sm[tid >> 5] = v;
    __syncthreads();
    const int flat = blockIdx.x + GX * (blockIdx.y + GY * blockIdx.z);
    if (tid < 16) {
        float t = sm[tid];
        #pragma unroll
        for (int o = 8; o; o >>= 1) t += __shfl_down_sync(0xffffu, t, o);
        if (tid == 0) g_block[flat] = t;
    }

    // ---- Last block finalizes ----
    __threadfence();
    if (tid == 0) {
        int old = atomicAdd(&g_count, 1);
        s_last = (old == NBLK - 1);
    }
    __syncthreads();
    if (s_last) {
        double d = (tid < NBLK) ? (double)g_block[tid] : 0.0;
        #pragma unroll
        for (int o = 16; o; o >>= 1) d += __shfl_down_sync(0xffffffffu, d, o);
        if ((tid & 31) == 0) wsd[tid >> 5] = d;
        __syncthreads();
        if (tid < 16) {
            double t2 = wsd[tid];
            #pragma unroll
            for (int o = 8; o; o >>= 1) t2 += __shfl_down_sync(0xffffu, t2, o);
            if (tid == 0) {
                out[0] = (float)(-t2 / (double)NTOT);
                g_count = 0;
            }
        }
    }
}

namespace {
struct KInit {
    KInit() {
        setenv("CUDA_MODULE_LOADING", "EAGER", 1);
        cudaFuncSetAttribute(lncc_fused_kernel,
                             cudaFuncAttributeMaxDynamicSharedMemorySize, SMEM_BYTES);
        cudaFuncAttributes a;
        cudaFuncGetAttributes(&a, lncc_fused_kernel);
    }
};
KInit kinit_;
}

extern "C" void kernel_launch(void* const* d_in, const int* in_sizes, int n_in,
                              void* d_out, int out_size)
{
    const float* y_true = (const float*)d_in[0];
    const float* y_pred = (const float*)d_in[1];
    float* out = (float*)d_out;
    (void)in_sizes; (void)n_in; (void)out_size;

    cudaFuncSetAttribute(lncc_fused_kernel,
                         cudaFuncAttributeMaxDynamicSharedMemorySize, SMEM_BYTES);
    dim3 grid(GX, GY, CZ * NB);
    lncc_fused_kernel<<<grid, 512, SMEM_BYTES>>>(y_true, y_pred, out);
}